// round 3
// baseline (speedup 1.0000x reference)
#include <cuda_runtime.h>
#include <math.h>

// Problem constants
#define SS 64
#define BB 32
#define DM 586
#define DE 583
#define NL 4
#define K1 17
#define CO1 16
#define P1LEN 114
#define KP 21       // combined conv1+pool kernel length
#define CO2 8
#define P2LEN 38
#define CO3 32
#define T3 36
#define NV 128
#define XSTR 180    // smem x row stride in kC

// Scratch (no allocations allowed)
__device__ float g_A[SS];
__device__ float g_C[SS];
__device__ float g_w1ps[BB*KP*16];    // [ci*21+m][co]  (co-fastest, conflict-free LDS)
__device__ float g_wsum1[CO1];
__device__ float g_out1p[SS*CO1*P1LEN];

// ---------------------------------------------------------------------------
// Kernel S (blocks 0..63): per-s stats straight from emb (warp per row),
// fold 4 BN layers into per-s affine (A,C).
// Kernel S (blocks 64..79): build combined conv1+pool weights for co = bx-64
// and wsum1[co] = sum of raw w1[co] (exact via pooling coverage identity).
// ---------------------------------------------------------------------------
__global__ void __launch_bounds__(1024)
kS(const int* __restrict__ tokens, const float* __restrict__ emb,
   const float* __restrict__ pos,
   const float* __restrict__ gamma, const float* __restrict__ beta,
   const float* __restrict__ w1) {
    int tid  = threadIdx.x;
    int wid  = tid >> 5;
    int lane = tid & 31;

    if (blockIdx.x < SS) {
        int s = blockIdx.x;
        const float scale = sqrtf(586.0f);
        // warp wid owns row b = wid
        int tok = tokens[s*BB + wid];
        const float* row = emb + (size_t)tok * DE;
        float sum = 0.f, sq = 0.f;
        #pragma unroll 5
        for (int d = lane; d < DE; d += 32) {
            float v = row[d] * scale;
            sum += v; sq += v*v;
        }
        if (lane < 3) {
            float v = pos[(s*BB + wid)*3 + lane];
            sum += v; sq += v*v;
        }
        #pragma unroll
        for (int off = 16; off >= 1; off >>= 1) {
            sum += __shfl_down_sync(0xffffffffu, sum, off);
            sq  += __shfl_down_sync(0xffffffffu, sq,  off);
        }
        __shared__ float shs[64];
        if (lane == 0) { shs[wid] = sum; shs[32 + wid] = sq; }
        __syncthreads();
        if (tid == 0) {
            float ts = 0.f, tq = 0.f;
            #pragma unroll
            for (int i = 0; i < 32; i++) { ts += shs[i]; tq += shs[32+i]; }
            float invN = 1.f / (float)(BB*DM);
            float m = ts * invN;
            float v = tq * invN - m*m;   // biased var, matches reference
            float A = 1.f, C = 0.f;
            #pragma unroll
            for (int l = 0; l < NL; l++) {
                float g  = gamma[l*SS + s];
                float bb = beta[l*SS + s];
                float inv = rsqrtf(v + 1e-5f);
                float a = g * inv;
                float c = bb - a * m;
                A = a * A;
                C = a * C + c;
                m = bb;          // mean after this BN layer
                v = a * a * v;   // var  after this BN layer
            }
            g_A[s] = A; g_C[s] = C;
        }
    } else {
        // weight prep for one output channel
        int co = blockIdx.x - SS;
        const float* wrow = w1 + co*BB*K1;   // 544 floats
        // combined weights: w1p[ci][m] = 0.2 * sum_j w1[ci][m-j], j in [max(0,m-16), min(4,m)]
        if (tid < BB*KP) {
            int ci = tid / KP;
            int m  = tid - ci*KP;
            int jlo = m - (K1-1); if (jlo < 0) jlo = 0;
            int jhi = m;          if (jhi > 4) jhi = 4;
            float acc = 0.f;
            for (int j = jlo; j <= jhi; j++)
                acc += wrow[ci*K1 + (m - j)];
            g_w1ps[tid*16 + co] = acc * 0.2f;
        }
        // wsum1[co] = sum of all 544 raw weights (each tap covered 5x * 1/5)
        float p = (tid < BB*K1) ? wrow[tid] : 0.f;
        #pragma unroll
        for (int off = 16; off >= 1; off >>= 1)
            p += __shfl_down_sync(0xffffffffu, p, off);
        __shared__ float shw[32];
        if (lane == 0) shw[wid] = p;
        __syncthreads();
        if (wid == 0) {
            float q = shw[lane];
            #pragma unroll
            for (int off = 16; off >= 1; off >>= 1)
                q += __shfl_down_sync(0xffffffffu, q, off);
            if (lane == 0) g_wsum1[co] = q;
        }
    }
}

// ---------------------------------------------------------------------------
// Kernel C: fused conv1+avgpool1 as a stride-5, K=21 conv, gathering its
// input slice DIRECTLY from emb/pos (L2-warm from kS).
// grid = 256 (64 s x 4 p-chunks of {29,29,28,28}), block = 128.
// Register tile: 2 co x 2 p. BN affine (A,C) folded into epilogue.
// ---------------------------------------------------------------------------
__global__ void kC(const int* __restrict__ tokens, const float* __restrict__ emb,
                   const float* __restrict__ pos, const float* __restrict__ b1) {
    int bx = blockIdx.x;
    int s  = bx >> 2;
    int cc = bx & 3;
    int p0 = (cc < 2) ? cc*29 : 58 + (cc-2)*28;
    int CH = (cc < 2) ? 29 : 28;
    int d0 = p0 * 5;
    int span = (CH-1)*5 + KP;  // 161 or 156 valid input cols

    extern __shared__ float sm[];
    float* xs = sm;                    // BB * XSTR
    float* ws = sm + BB*XSTR;          // 672 * 16

    int tid = threadIdx.x;
    const float scale = sqrtf(586.0f);
    // Gather x slice straight from emb/pos (zero-padded to XSTR)
    #pragma unroll 4
    for (int idx = tid; idx < BB*XSTR; idx += 128) {
        int ci = idx / XSTR;
        int dd = idx - ci*XSTR;
        float v = 0.f;
        if (dd < span) {
            int d = d0 + dd;
            if (d < DE) {
                int tok = tokens[s*BB + ci];
                v = emb[(size_t)tok*DE + d] * scale;
            } else {
                v = pos[(s*BB + ci)*3 + (d - DE)];
            }
        }
        xs[idx] = v;
    }
    // Load combined weights (vectorized)
    {
        const float4* wsrc = (const float4*)g_w1ps;
        float4* wdst = (float4*)ws;
        for (int idx = tid; idx < BB*KP*4; idx += 128) wdst[idx] = wsrc[idx];
    }
    __syncthreads();

    int pt  = tid >> 3;   // 0..15 ; warp spans 4 pt -> x LDS stride 10 words, conflict-free
    int cop = tid & 7;    // 0..7 co-pairs
    int pl0 = pt * 2;
    int co0 = cop * 2;
    float acc00 = 0.f, acc01 = 0.f, acc10 = 0.f, acc11 = 0.f;
    const float* xbase = xs + 5*pl0;
    #pragma unroll 2
    for (int ci = 0; ci < BB; ci++) {
        const float* xr = xbase + ci*XSTR;
        float xw[26];
        #pragma unroll
        for (int i = 0; i < 26; i++) xw[i] = xr[i];
        const float* wp = ws + ci*KP*16 + co0;
        #pragma unroll
        for (int m = 0; m < KP; m++) {
            float2 w = *(const float2*)(wp + m*16);
            float x0v = xw[m];
            float x1v = xw[m+5];
            acc00 += w.x * x0v;
            acc01 += w.y * x0v;
            acc10 += w.x * x1v;
            acc11 += w.y * x1v;
        }
    }
    float A  = g_A[s];
    float Cc = g_C[s];
    float bias0 = Cc * g_wsum1[co0]   + b1[co0];
    float bias1 = Cc * g_wsum1[co0+1] + b1[co0+1];
    if (pl0 < CH) {
        int p = p0 + pl0;
        g_out1p[(s*CO1 + co0  )*P1LEN + p] = A*acc00 + bias0;
        g_out1p[(s*CO1 + co0+1)*P1LEN + p] = A*acc01 + bias1;
    }
    if (pl0 + 1 < CH) {
        int p = p0 + pl0 + 1;
        g_out1p[(s*CO1 + co0  )*P1LEN + p] = A*acc10 + bias0;
        g_out1p[(s*CO1 + co0+1)*P1LEN + p] = A*acc11 + bias1;
    }
}

// ---------------------------------------------------------------------------
// Kernel D: avgpool2 -> conv2(1x1) -> conv3(K=3) -> proj(128x36) -> argmax.
// grid = 64 (one per s), block = 256.
// ---------------------------------------------------------------------------
__global__ void kD(const float* __restrict__ w2, const float* __restrict__ b2,
                   const float* __restrict__ w3, const float* __restrict__ b3,
                   const float* __restrict__ wl, const float* __restrict__ bl,
                   float* __restrict__ out) {
    int s = blockIdx.x;
    int tid = threadIdx.x;
    __shared__ float o1[CO1*P1LEN];
    __shared__ float wls[NV*T3];
    __shared__ float bls[NV];
    __shared__ float o2[CO2*P2LEN];
    __shared__ float o3[CO3*T3];

    for (int i = tid; i < CO1*P1LEN; i += 256) o1[i] = g_out1p[s*CO1*P1LEN + i];
    for (int i = tid; i < NV*T3;    i += 256) wls[i] = wl[i];
    if (tid < NV) bls[tid] = bl[tid];
    __syncthreads();

    // avgpool(3) then conv2 1x1 (commutes with reference conv2->pool)
    for (int i = tid; i < CO2*P2LEN; i += 256) {
        int c8 = i / P2LEN;
        int q  = i - c8*P2LEN;
        float acc = 0.f;
        #pragma unroll
        for (int ci = 0; ci < CO1; ci++) {
            const float* r = o1 + ci*P1LEN + 3*q;
            acc += w2[c8*CO1 + ci] * (r[0] + r[1] + r[2]);
        }
        o2[i] = acc * (1.f/3.f) + b2[c8];
    }
    __syncthreads();

    // conv3: (8,38) -> (32,36), K=3
    for (int i = tid; i < CO3*T3; i += 256) {
        int co = i / T3;
        int t  = i - co*T3;
        float acc = b3[co];
        #pragma unroll
        for (int c8 = 0; c8 < CO2; c8++) {
            const float* r = o2 + c8*P2LEN + t;
            const float* w = w3 + (co*CO2 + c8)*3;
            acc += w[0]*r[0] + w[1]*r[1] + w[2]*r[2];
        }
        o3[i] = acc;
    }
    __syncthreads();

    // projection to 128 vocab + argmax (first-max semantics like jnp.argmax)
    int c  = tid >> 3;
    int vl = tid & 7;
    float orow[T3];
    #pragma unroll
    for (int k = 0; k < T3; k++) orow[k] = o3[c*T3 + k];

    float bestv = -3.4e38f;
    int   besti = 0;
    #pragma unroll 2
    for (int i = 0; i < 16; i++) {
        int v = vl + 8*i;
        float d = bls[v];
        const float* wr = wls + v*T3;
        #pragma unroll
        for (int k = 0; k < T3; k++) d += orow[k] * wr[k];
        if (d > bestv) { bestv = d; besti = v; }  // strict > keeps first max within lane
    }
    #pragma unroll
    for (int off = 4; off >= 1; off >>= 1) {
        float ov = __shfl_down_sync(0xffffffffu, bestv, off);
        int   oi = __shfl_down_sync(0xffffffffu, besti, off);
        if (ov > bestv || (ov == bestv && oi < besti)) { bestv = ov; besti = oi; }
    }
    if (vl == 0) out[s*BB + c] = (float)besti;
}

// ---------------------------------------------------------------------------
extern "C" void kernel_launch(void* const* d_in, const int* in_sizes, int n_in,
                              void* d_out, int out_size) {
    const int*   tokens = (const int*)  d_in[0];
    const float* emb    = (const float*)d_in[1];
    const float* pos    = (const float*)d_in[2];
    const float* gamma  = (const float*)d_in[3];
    const float* beta   = (const float*)d_in[4];
    const float* w1     = (const float*)d_in[5];
    const float* b1     = (const float*)d_in[6];
    const float* w2     = (const float*)d_in[7];
    const float* b2     = (const float*)d_in[8];
    const float* w3     = (const float*)d_in[9];
    const float* b3     = (const float*)d_in[10];
    const float* wl     = (const float*)d_in[11];
    const float* bl     = (const float*)d_in[12];
    float* out = (float*)d_out;

    size_t shC = (size_t)(BB*XSTR + BB*KP*16) * sizeof(float);  // ~66 KB
    cudaFuncSetAttribute(kC, cudaFuncAttributeMaxDynamicSharedMemorySize, (int)shC);

    kS<<<SS + CO1, 1024>>>(tokens, emb, pos, gamma, beta, w1);
    kC<<<256, 128, shC>>>(tokens, emb, pos, b1);
    kD<<<SS, 256>>>(w2, b2, w3, b3, wl, bl, out);
}

// round 4
// speedup vs baseline: 1.2538x; 1.2538x over previous
#include <cuda_runtime.h>
#include <math.h>

// Problem constants
#define SS 64
#define BB 32
#define DM 586
#define DE 583
#define NL 4
#define K1 17
#define CO1 16
#define P1LEN 114
#define KP 21       // combined conv1+pool kernel length
#define CO2 8
#define P2LEN 38
#define CO3 32
#define T3 36
#define NV 128
#define XSTR 180    // smem x row stride in kC

// Scratch (no allocations allowed)
__device__ float g_x0[SS*BB*DM];
__device__ float g_part[SS*2*2];      // per (s, half): {sum, sumsq}
__device__ float g_w1ps[BB*KP*16];    // [ci*21+m][co]  (co-fastest, conflict-free LDS)
__device__ float g_wsum1[CO1];
__device__ float g_out1p[SS*CO1*P1LEN];

// ---------------------------------------------------------------------------
// Kernel S (blocks 0..127): embedding gather (*sqrt(D)) + pos -> g_x0, and
// partial per-s sums. Block bx handles s = bx>>1, rows [16*(bx&1), +16).
// 1024 threads = 32 warps; 2 warps per row, each striding 64.
// Kernel S (blocks 128..143): combined conv1+pool weights for co = bx-128
// and wsum1[co] = sum of raw w1[co] (pooling coverage identity).
// ---------------------------------------------------------------------------
__global__ void __launch_bounds__(1024)
kS(const int* __restrict__ tokens, const float* __restrict__ emb,
   const float* __restrict__ pos, const float* __restrict__ w1) {
    int tid  = threadIdx.x;
    int wid  = tid >> 5;
    int lane = tid & 31;

    if (blockIdx.x < 2*SS) {
        int s    = blockIdx.x >> 1;
        int half = blockIdx.x & 1;
        const float scale = sqrtf(586.0f);
        int b    = half*16 + (wid >> 1);   // row within batch
        int part = wid & 1;                // which half of the row this warp covers
        int tok  = tokens[s*BB + b];
        const float* row = emb + (size_t)tok * DE;
        float* xrow = g_x0 + (size_t)(s*BB + b) * DM;
        float sum = 0.f, sq = 0.f;
        int d = lane + 32*part;
        #pragma unroll 3
        for (; d < DE; d += 64) {
            float v = row[d] * scale;
            xrow[d] = v;
            sum += v; sq += v*v;
        }
        if (part == 0 && lane < 3) {
            float v = pos[(s*BB + b)*3 + lane];
            xrow[DE + lane] = v;
            sum += v; sq += v*v;
        }
        #pragma unroll
        for (int off = 16; off >= 1; off >>= 1) {
            sum += __shfl_down_sync(0xffffffffu, sum, off);
            sq  += __shfl_down_sync(0xffffffffu, sq,  off);
        }
        __shared__ float shs[64];
        if (lane == 0) { shs[wid] = sum; shs[32 + wid] = sq; }
        __syncthreads();
        if (wid == 0) {
            float a = shs[lane];
            float c = shs[32 + lane];
            #pragma unroll
            for (int off = 16; off >= 1; off >>= 1) {
                a += __shfl_down_sync(0xffffffffu, a, off);
                c += __shfl_down_sync(0xffffffffu, c, off);
            }
            if (lane == 0) {
                g_part[(s*2 + half)*2 + 0] = a;
                g_part[(s*2 + half)*2 + 1] = c;
            }
        }
    } else {
        // weight prep for one output channel
        int co = blockIdx.x - 2*SS;
        const float* wrow = w1 + co*BB*K1;   // 544 floats
        // combined weights: w1p[ci][m] = 0.2 * sum_j w1[ci][m-j], j in [max(0,m-16), min(4,m)]
        if (tid < BB*KP) {
            int ci = tid / KP;
            int m  = tid - ci*KP;
            int jlo = m - (K1-1); if (jlo < 0) jlo = 0;
            int jhi = m;          if (jhi > 4) jhi = 4;
            float acc = 0.f;
            for (int j = jlo; j <= jhi; j++)
                acc += wrow[ci*K1 + (m - j)];
            g_w1ps[tid*16 + co] = acc * 0.2f;
        }
        // wsum1[co] = sum of all 544 raw weights (each tap covered 5x * 1/5)
        float p = (tid < BB*K1) ? wrow[tid] : 0.f;
        #pragma unroll
        for (int off = 16; off >= 1; off >>= 1)
            p += __shfl_down_sync(0xffffffffu, p, off);
        __shared__ float shw[32];
        if (lane == 0) shw[wid] = p;
        __syncthreads();
        if (wid == 0) {
            float q = shw[lane];
            #pragma unroll
            for (int off = 16; off >= 1; off >>= 1)
                q += __shfl_down_sync(0xffffffffu, q, off);
            if (lane == 0) g_wsum1[co] = q;
        }
    }
}

// ---------------------------------------------------------------------------
// Kernel C: fused conv1+avgpool1 as a stride-5, K=21 conv on g_x0.
// grid = 256 (64 s x 4 p-chunks of {29,29,28,28}), block = 128.
// Register tile: 2 co x 2 p. BN affine computed inline from g_part + gamma/beta
// and folded into the epilogue.
// ---------------------------------------------------------------------------
__global__ void kC(const float* __restrict__ gamma, const float* __restrict__ beta,
                   const float* __restrict__ b1) {
    int bx = blockIdx.x;
    int s  = bx >> 2;
    int cc = bx & 3;
    int p0 = (cc < 2) ? cc*29 : 58 + (cc-2)*28;
    int CH = (cc < 2) ? 29 : 28;
    int d0 = p0 * 5;
    int span = (CH-1)*5 + KP;  // 161 or 156 valid input cols

    extern __shared__ float sm[];
    float* xs = sm;                    // BB * XSTR
    float* ws = sm + BB*XSTR;          // 672 * 16

    int tid = threadIdx.x;
    // Load x slice (span valid cols per ci, zero-padded to XSTR)
    for (int idx = tid; idx < BB*XSTR; idx += 128) {
        int ci = idx / XSTR;
        int dd = idx - ci*XSTR;
        float v = 0.f;
        if (dd < span) v = g_x0[(s*BB + ci)*DM + d0 + dd];
        xs[idx] = v;
    }
    // Load combined weights (vectorized)
    {
        const float4* wsrc = (const float4*)g_w1ps;
        float4* wdst = (float4*)ws;
        for (int idx = tid; idx < BB*KP*4; idx += 128) wdst[idx] = wsrc[idx];
    }
    __syncthreads();

    int pt  = tid >> 3;   // 0..15 ; warp spans 4 pt -> x LDS stride 10 words, conflict-free
    int cop = tid & 7;    // 0..7 co-pairs
    int pl0 = pt * 2;
    int co0 = cop * 2;
    float acc00 = 0.f, acc01 = 0.f, acc10 = 0.f, acc11 = 0.f;
    const float* xbase = xs + 5*pl0;
    #pragma unroll 2
    for (int ci = 0; ci < BB; ci++) {
        const float* xr = xbase + ci*XSTR;
        float xw[26];
        #pragma unroll
        for (int i = 0; i < 26; i++) xw[i] = xr[i];
        const float* wp = ws + ci*KP*16 + co0;
        #pragma unroll
        for (int m = 0; m < KP; m++) {
            float2 w = *(const float2*)(wp + m*16);
            float x0v = xw[m];
            float x1v = xw[m+5];
            acc00 += w.x * x0v;
            acc01 += w.y * x0v;
            acc10 += w.x * x1v;
            acc11 += w.y * x1v;
        }
    }
    // BN affine fold (redundant per thread; broadcast loads, ~30 flops)
    float A, Cf;
    {
        float invN = 1.f / (float)(BB*DM);
        float ts = g_part[s*4 + 0] + g_part[s*4 + 2];
        float tq = g_part[s*4 + 1] + g_part[s*4 + 3];
        float m = ts * invN;
        float v = tq * invN - m*m;   // biased var, matches reference
        A = 1.f; Cf = 0.f;
        #pragma unroll
        for (int l = 0; l < NL; l++) {
            float g  = gamma[l*SS + s];
            float bb = beta[l*SS + s];
            float inv = rsqrtf(v + 1e-5f);
            float a = g * inv;
            float c = bb - a * m;
            A = a * A;
            Cf = a * Cf + c;
            m = bb;          // mean after this BN layer
            v = a * a * v;   // var  after this BN layer
        }
    }
    float bias0 = Cf * g_wsum1[co0]   + b1[co0];
    float bias1 = Cf * g_wsum1[co0+1] + b1[co0+1];
    if (pl0 < CH) {
        int p = p0 + pl0;
        g_out1p[(s*CO1 + co0  )*P1LEN + p] = A*acc00 + bias0;
        g_out1p[(s*CO1 + co0+1)*P1LEN + p] = A*acc01 + bias1;
    }
    if (pl0 + 1 < CH) {
        int p = p0 + pl0 + 1;
        g_out1p[(s*CO1 + co0  )*P1LEN + p] = A*acc10 + bias0;
        g_out1p[(s*CO1 + co0+1)*P1LEN + p] = A*acc11 + bias1;
    }
}

// ---------------------------------------------------------------------------
// Kernel D: avgpool2 -> conv2(1x1) -> conv3(K=3) -> proj(128x36) -> argmax.
// grid = 64 (one per s), block = 256.
// ---------------------------------------------------------------------------
__global__ void kD(const float* __restrict__ w2, const float* __restrict__ b2,
                   const float* __restrict__ w3, const float* __restrict__ b3,
                   const float* __restrict__ wl, const float* __restrict__ bl,
                   float* __restrict__ out) {
    int s = blockIdx.x;
    int tid = threadIdx.x;
    __shared__ float o1[CO1*P1LEN];
    __shared__ float wls[NV*T3];
    __shared__ float bls[NV];
    __shared__ float o2[CO2*P2LEN];
    __shared__ float o3[CO3*T3];

    for (int i = tid; i < CO1*P1LEN; i += 256) o1[i] = g_out1p[s*CO1*P1LEN + i];
    for (int i = tid; i < NV*T3;    i += 256) wls[i] = wl[i];
    if (tid < NV) bls[tid] = bl[tid];
    __syncthreads();

    // avgpool(3) then conv2 1x1 (commutes with reference conv2->pool)
    for (int i = tid; i < CO2*P2LEN; i += 256) {
        int c8 = i / P2LEN;
        int q  = i - c8*P2LEN;
        float acc = 0.f;
        #pragma unroll
        for (int ci = 0; ci < CO1; ci++) {
            const float* r = o1 + ci*P1LEN + 3*q;
            acc += w2[c8*CO1 + ci] * (r[0] + r[1] + r[2]);
        }
        o2[i] = acc * (1.f/3.f) + b2[c8];
    }
    __syncthreads();

    // conv3: (8,38) -> (32,36), K=3
    for (int i = tid; i < CO3*T3; i += 256) {
        int co = i / T3;
        int t  = i - co*T3;
        float acc = b3[co];
        #pragma unroll
        for (int c8 = 0; c8 < CO2; c8++) {
            const float* r = o2 + c8*P2LEN + t;
            const float* w = w3 + (co*CO2 + c8)*3;
            acc += w[0]*r[0] + w[1]*r[1] + w[2]*r[2];
        }
        o3[i] = acc;
    }
    __syncthreads();

    // projection to 128 vocab + argmax (first-max semantics like jnp.argmax)
    int c  = tid >> 3;
    int vl = tid & 7;
    float orow[T3];
    #pragma unroll
    for (int k = 0; k < T3; k++) orow[k] = o3[c*T3 + k];

    float bestv = -3.4e38f;
    int   besti = 0;
    #pragma unroll 2
    for (int i = 0; i < 16; i++) {
        int v = vl + 8*i;
        float d = bls[v];
        const float* wr = wls + v*T3;
        #pragma unroll
        for (int k = 0; k < T3; k++) d += orow[k] * wr[k];
        if (d > bestv) { bestv = d; besti = v; }  // strict > keeps first max within lane
    }
    #pragma unroll
    for (int off = 4; off >= 1; off >>= 1) {
        float ov = __shfl_down_sync(0xffffffffu, bestv, off);
        int   oi = __shfl_down_sync(0xffffffffu, besti, off);
        if (ov > bestv || (ov == bestv && oi < besti)) { bestv = ov; besti = oi; }
    }
    if (vl == 0) out[s*BB + c] = (float)besti;
}

// ---------------------------------------------------------------------------
extern "C" void kernel_launch(void* const* d_in, const int* in_sizes, int n_in,
                              void* d_out, int out_size) {
    const int*   tokens = (const int*)  d_in[0];
    const float* emb    = (const float*)d_in[1];
    const float* pos    = (const float*)d_in[2];
    const float* gamma  = (const float*)d_in[3];
    const float* beta   = (const float*)d_in[4];
    const float* w1     = (const float*)d_in[5];
    const float* b1     = (const float*)d_in[6];
    const float* w2     = (const float*)d_in[7];
    const float* b2     = (const float*)d_in[8];
    const float* w3     = (const float*)d_in[9];
    const float* b3     = (const float*)d_in[10];
    const float* wl     = (const float*)d_in[11];
    const float* bl     = (const float*)d_in[12];
    float* out = (float*)d_out;

    size_t shC = (size_t)(BB*XSTR + BB*KP*16) * sizeof(float);  // ~66 KB
    cudaFuncSetAttribute(kC, cudaFuncAttributeMaxDynamicSharedMemorySize, (int)shC);

    kS<<<2*SS + CO1, 1024>>>(tokens, emb, pos, w1);
    kC<<<256, 128, shC>>>(gamma, beta, b1);
    kD<<<SS, 256>>>(w2, b2, w3, b3, wl, bl, out);
}